// round 9
// baseline (speedup 1.0000x reference)
#include <cuda_runtime.h>
#include <stdint.h>

#define NB 8
#define NC 19
#define HW (512 * 512)        // pixels per batch
#define CPX 256               // pixels per chunk (K of one pipeline stage)
#define NCH (HW / CPX)        // 1024 chunks per batch
#define BX 37                 // CTAs per batch (37*8 = 296 = one wave @ 2/SM)
#define ARF 260               // f32 row stride (260 % 32 == 4 -> conflict-free LDS)
#define NSTG 3                // pipeline stages

#define ABYTES (20 * ARF)                 // floats per A stage (row 19 = ones)
#define SMEM_FLOATS (NSTG * ABYTES + NSTG * 512 + 20 * 24)
#define SMEM_BYTES (SMEM_FLOATS * 4)      // ~67.3 KB

// Scratch (no allocations allowed)
__device__ float g_S[NB * NC * NC];   // S[b,i,k] = sum_p z[b,i,p]*[label_p==k]
__device__ float g_cnt[NB * NC];      // cnt[b,k]
__device__ int   g_mode64;            // labels stored as int64?

// ---------------------------------------------------------------------------
// Kernel 0: zero scratch (grid-stride) + sampled label-dtype sniff.
// ---------------------------------------------------------------------------
__global__ void __launch_bounds__(256)
setup_kernel(const int* __restrict__ lab32) {
    int t = blockIdx.x * blockDim.x + threadIdx.x;
    int nthreads = gridDim.x * blockDim.x;

    for (int i = t; i < NB * NC * NC; i += nthreads) g_S[i] = 0.0f;
    for (int i = t; i < NB * NC; i += nthreads)      g_cnt[i] = 0.0f;
    if (t == 0) g_mode64 = 1;

    int acc = 0;
    for (int i = t; i < 2048; i += nthreads)
        acc |= lab32[2 * i + 1];
#pragma unroll
    for (int s = 16; s > 0; s >>= 1)
        acc |= __shfl_xor_sync(0xffffffffu, acc, s);
    if ((threadIdx.x & 31) == 0 && acc != 0)
        atomicExch(&g_mode64, 0);
}

// ---------------------------------------------------------------------------
#define CVT_TF32(d, f) asm("cvt.rna.tf32.f32 %0, %1;" : "=r"(d) : "f"(f))

#define MMA_TF32(ac, A0, A1, A2, A3, B0, B1)                                  \
    asm volatile("mma.sync.aligned.m16n8k8.row.col.f32.tf32.tf32.f32 "        \
                 "{%0,%1,%2,%3}, {%4,%5,%6,%7}, {%8,%9}, {%0,%1,%2,%3};"      \
                 : "+f"((ac)[0]), "+f"((ac)[1]), "+f"((ac)[2]), "+f"((ac)[3]) \
                 : "r"(A0), "r"(A1), "r"(A2), "r"(A3), "r"(B0), "r"(B1))

__device__ __forceinline__ void cp16(void* sdst, const void* gsrc) {
    uint32_t s = (uint32_t)__cvta_generic_to_shared(sdst);
    asm volatile("cp.async.cg.shared.global [%0], [%1], 16;" :: "r"(s), "l"(gsrc));
}

// ---------------------------------------------------------------------------
// Kernel 1: per-batch GEMM  S[32,24] += Z_chunk[20,256] * Onehot[256,24]
// tf32 mma, 3-stage cp.async pipeline, ONE barrier per chunk.
// A rows: 0..18 = channels, 19 = ones (-> cnt), 20..31 implicit zero (never
// flushed; rows 20..23 read clamped row 19, results discarded).
// ---------------------------------------------------------------------------
__global__ void __launch_bounds__(256, 2)
gemm_scatter_kernel(const float* __restrict__ seg, const int* __restrict__ lab32) {
    extern __shared__ __align__(16) float smem[];
    float* Abuf[NSTG];
    int*   Lbuf[NSTG];
#pragma unroll
    for (int s = 0; s < NSTG; s++) {
        Abuf[s] = smem + s * ABYTES;
        Lbuf[s] = (int*)(smem + NSTG * ABYTES) + s * 512;
    }
    float* S_red = smem + NSTG * ABYTES + NSTG * 512;   // [20][24]

    const int tid  = threadIdx.x;
    const int lane = tid & 31;
    const int wid  = tid >> 5;
    const int b    = blockIdx.y;
    const int mode64 = g_mode64;

    const float* zb = seg + (size_t)b * NC * HW;
    const int*   lb = lab32 + ((size_t)b * HW << mode64);

    for (int i = tid; i < 20 * 24; i += 256) S_red[i] = 0.0f;
    // ones row (row 19) of every stage buffer — written once, rows 0..18 only
    // are touched by prefetch, so no overlap.
    for (int i = tid; i < NSTG * ARF; i += 256)
        Abuf[i / ARF][19 * ARF + (i % ARF)] = 1.0f;

    float acc1[3][4], acc2[3][4];
#pragma unroll
    for (int n = 0; n < 3; n++)
#pragma unroll
        for (int f = 0; f < 4; f++) { acc1[n][f] = 0.0f; acc2[n][f] = 0.0f; }

    auto prefetch = [&](int T, int buf) {
        if (T < NCH) {
            const int tpx = T * CPX;
            float* A = Abuf[buf];
            for (int idx = tid; idx < NC * 64; idx += 256) {   // 1216 float4 groups
                int c = idx >> 6, j = idx & 63;
                cp16(A + c * ARF + 4 * j, zb + (size_t)c * HW + tpx + 4 * j);
            }
            if (mode64) {
                if (tid < 128) cp16(Lbuf[buf] + 4 * tid, lb + (size_t)tpx * 2 + 4 * tid);
            } else {
                if (tid < 64)  cp16(Lbuf[buf] + 4 * tid, lb + tpx + 4 * tid);
            }
        }
        asm volatile("cp.async.commit_group;");   // uniform commit, even if empty
    };

    const int T0 = blockIdx.x;
    prefetch(T0, 0);
    prefetch(T0 + BX, 1);

    // per-thread fragment geometry
    const int g  = lane >> 2;              // 0..7
    const int c4 = lane & 3;               // 0..3
    const int wbase = wid * 32;            // this warp's 32-pixel k-slice
    const int r2 = 16 + g;                 // mtile2 logical row (16..23)
    const int r2c = (r2 < 20) ? r2 : 19;   // clamp: rows 20..23 read ones row

    int m = 0;
    for (int T = T0; T < NCH; T += BX, m++) {
        const int buf = m % NSTG;
        asm volatile("cp.async.wait_group %0;" :: "n"(NSTG - 2));
        __syncthreads();   // sole barrier: data ready AND prev buffer free

        const float* A = Abuf[buf];
        const int*   L = Lbuf[buf];
        const float* pA  = A + g * ARF + c4;
        const float* pA8 = A + (g + 8) * ARF + c4;
        const float* pA2 = A + r2c * ARF + c4;

#pragma unroll
        for (int ks = 0; ks < 4; ks++) {
            const int kb = wbase + ks * 8;

            float f0 = pA[kb], f1 = pA8[kb], f2 = pA[kb + 4], f3 = pA8[kb + 4];
            float h0 = pA2[kb], h2 = pA2[kb + 4];

            uint32_t a0, a1, a2, a3, e0, e2;
            CVT_TF32(a0, f0); CVT_TF32(a1, f1);
            CVT_TF32(a2, f2); CVT_TF32(a3, f3);
            CVT_TF32(e0, h0); CVT_TF32(e2, h2);

            const int lA = L[(kb + c4) << mode64];
            const int lB = L[(kb + c4 + 4) << mode64];

#pragma unroll
            for (int nt = 0; nt < 3; nt++) {
                const int n = g + nt * 8;
                uint32_t b0 = (lA == n) ? 0x3F800000u : 0u;
                uint32_t b1 = (lB == n) ? 0x3F800000u : 0u;
                MMA_TF32(acc1[nt], a0, a1, a2, a3, b0, b1);
                MMA_TF32(acc2[nt], e0, 0u, e2, 0u, b0, b1);
            }
        }

        // refill the buffer freed by the barrier above (used at iter m+2)
        prefetch(T + 2 * BX, (m + 2) % NSTG);
    }

    // ---- CTA reduction into S_red ----
    __syncthreads();
    {
        const int cc = c4 * 2;
#pragma unroll
        for (int nt = 0; nt < 3; nt++) {
            const int nb8 = nt * 8 + cc;
            atomicAdd(&S_red[g * 24 + nb8],           acc1[nt][0]);
            atomicAdd(&S_red[g * 24 + nb8 + 1],       acc1[nt][1]);
            atomicAdd(&S_red[(g + 8) * 24 + nb8],     acc1[nt][2]);
            atomicAdd(&S_red[(g + 8) * 24 + nb8 + 1], acc1[nt][3]);
            if (r2 < 20) {   // rows 16..19 only (20..23 are clamped duplicates)
                atomicAdd(&S_red[r2 * 24 + nb8],     acc2[nt][0]);
                atomicAdd(&S_red[r2 * 24 + nb8 + 1], acc2[nt][1]);
            }
        }
    }
    __syncthreads();

    // ---- global flush: rows 0..18 -> g_S, row 19 -> g_cnt ----
    for (int idx = tid; idx < 20 * NC; idx += 256) {
        int r = idx / NC, c = idx % NC;
        float v = S_red[r * 24 + c];
        if (r < NC) atomicAdd(&g_S[(b * NC + r) * NC + c], v);
        else        atomicAdd(&g_cnt[b * NC + c], v);
    }
}

// ---------------------------------------------------------------------------
// Kernel 2: finalize — 2888 log terms in double, write the scalar loss
// ---------------------------------------------------------------------------
__global__ void __launch_bounds__(256)
finalize_kernel(float* __restrict__ out) {
    __shared__ double red[256];
    const int tid = threadIdx.x;
    const double eps = 2.220446049250313e-16;  // np.spacing(1)

    double acc = 0.0;
    for (int idx = tid; idx < NB * NC * NC; idx += 256) {
        int b = idx / (NC * NC);
        int rem = idx % (NC * NC);
        int i = rem / NC, k = rem % NC;
        float cnt_i = g_cnt[b * NC + i];
        float cnt_k = g_cnt[b * NC + k];
        double alpha = (cnt_i > 0.0f)
            ? (double)g_S[(b * NC + i) * NC + i] / (double)cnt_i : 0.0;
        double beta = (cnt_k > 0.0f)
            ? ((double)cnt_k - (double)g_S[(b * NC + i) * NC + k]) / (double)cnt_k
            : 0.0;
        acc += log(0.5 * (alpha + beta + eps));
    }
    red[tid] = acc;
    __syncthreads();
    for (int s = 128; s > 0; s >>= 1) {
        if (tid < s) red[tid] += red[tid + s];
        __syncthreads();
    }
    if (tid == 0) out[0] = (float)(-0.5 * red[0] / (double)NB);
}

// ---------------------------------------------------------------------------
extern "C" void kernel_launch(void* const* d_in, const int* in_sizes, int n_in,
                              void* d_out, int out_size) {
    const float* seg;
    const int*   lab32;
    if (in_sizes[0] > in_sizes[1]) {
        seg   = (const float*)d_in[0];
        lab32 = (const int*)d_in[1];
    } else {
        seg   = (const float*)d_in[1];
        lab32 = (const int*)d_in[0];
    }
    float* out = (float*)d_out;

    cudaFuncSetAttribute(gemm_scatter_kernel,
                         cudaFuncAttributeMaxDynamicSharedMemorySize, SMEM_BYTES);

    setup_kernel<<<12, 256>>>(lab32);

    dim3 grid(BX, NB);
    gemm_scatter_kernel<<<grid, 256, SMEM_BYTES>>>(seg, lab32);

    finalize_kernel<<<1, 256>>>(out);
}